// round 9
// baseline (speedup 1.0000x reference)
#include <cuda_runtime.h>
#include <cuda_fp16.h>
#include <cstdint>

#define W_IMG 1216
#define H_IMG 352
#define NB    4
#define HW    (H_IMG * W_IMG)
#define CHG   27
#define PT    3
#define NOC   81                 /* conv output channels */
#define KDIM  256                /* MMA K (pad 243 -> 256) */
#define NT8   11                 /* n8 tiles: 88 >= 81 */

#define AST   264                /* A smem stride (halves): 528B rows, LDSM conflict-free */
#define RSTR  136                /* result staging stride (floats) */

/* ---- smem layout (bytes) ---- */
#define SM_A     0
#define SM_A_SZ  (128 * AST * 2)           /* 67584; Rs (96*136*4=52224) reuses it */
#define SM_B     SM_A_SZ
#define SM_B_SZ  (16 * NT8 * 32 * 8)       /* 45056: B in mma-fragment order */
#define SMEM_TOTAL (SM_B + SM_B_SZ)        /* 112640 -> 2 CTAs/SM */

/* B in fragment order: [ks][n8][lane][2 regs] */
__device__ uint32_t g_wbf[16 * NT8 * 32 * 2];
/* fp16 staging of offsets/affs for the prop kernels */
__device__ __half g_offh[(size_t)NB * PT * 18 * HW];
__device__ __half g_affh[(size_t)NB * PT * 9 * HW];
__device__ float g_sink;

__device__ __forceinline__ float h2(float x) {
    return __half2float(__float2half(x));
}
__device__ __forceinline__ uint32_t smem_u32(const void* p) {
    uint32_t a;
    asm("{ .reg .u64 t; cvta.to.shared.u64 t, %1; cvt.u32.u64 %0, t; }"
        : "=r"(a) : "l"(p));
    return a;
}

/* -------- reorder: B fragments for mma.m16n8k16 (row.col) -------- */
__global__ void reorder_kernel(const float* __restrict__ w_off) {
    int i = blockIdx.x * 256 + threadIdx.x;
    if (i >= 16 * NT8 * 32) return;
    int ks   = i / (NT8 * 32);
    int rem  = i - ks * (NT8 * 32);
    int n8   = rem >> 5;
    int lane = rem & 31;
    int tg   = lane & 3;
    int g8   = lane >> 2;
    int n    = n8 * 8 + g8;
    int k0   = ks * 16 + tg * 2;
    float v[4];
#pragma unroll
    for (int u = 0; u < 4; u++) {
        int k = k0 + (u >> 1) * 8 + (u & 1);
        v[u] = (n < NOC && k < 243) ? w_off[(size_t)n * 243 + k] : 0.f;
    }
    __half2 r0 = __floats2half2_rn(v[0], v[1]);
    __half2 r1 = __floats2half2_rn(v[2], v[3]);
    g_wbf[i * 2]     = *(uint32_t*)&r0;
    g_wbf[i * 2 + 1] = *(uint32_t*)&r1;
}

__global__ void dummy_kernel() { if (threadIdx.x == 0) g_sink = 0.f; }

/* ---------------------------------------------------------------
 * Conv 27->81 as raw mma.sync fp16 GEMM (M=128 px, N=88, K=256),
 * fused bias + fp16-round + softmax epilogue.
 * CTA tile: 2 rows x 64 px. 256 threads, 2 CTAs/SM.
 * --------------------------------------------------------------- */
__global__ void __launch_bounds__(256, 2)
conv_kernel(const float* __restrict__ g,
            const float* __restrict__ b_off,
            float* __restrict__ out_off,
            float* __restrict__ out_aff)
{
    extern __shared__ char smc[];
    __half*   As  = (__half*)(smc + SM_A);
    uint32_t* Bs  = (uint32_t*)(smc + SM_B);
    float*    Rs  = (float*)(smc + SM_A);
    const uint32_t smb = smem_u32(smc);

    const int tid  = threadIdx.x;
    const int wid  = tid >> 5;
    const int lane = tid & 31;
    const int x0   = blockIdx.x * 64;
    const int y0   = blockIdx.y * 2;
    const int b    = blockIdx.z;

    /* ---- B copy (fragment order, 2816 float4) ---- */
    {
        const float4* src = (const float4*)g_wbf;
        float4* dst = (float4*)Bs;
        for (int i = tid; i < SM_B_SZ / 16; i += 256) dst[i] = src[i];
    }

    /* ---- A build: im2col fp16 straight from global ---- */
    {
        const int px  = tid & 127;
        const int kh  = tid >> 7;
        const int r   = px >> 6;
        const int c   = px & 63;
        const int gyb = y0 - 1 + r;
        const int gxb = x0 - 1 + c;
        const float* gb = g + (size_t)b * CHG * HW;
        __half* arow = As + px * AST;
        const int K0 = kh ? 126 : 0;
        const int np = kh ? 65 : 63;
        for (int p = 0; p < np; p++) {
            int K = K0 + 2 * p;
            float v[2] = {0.f, 0.f};
#pragma unroll
            for (int u = 0; u < 2; u++) {
                int k = K + u;
                if (k < 243) {
                    int ic  = k / 9;
                    int tap = k - ic * 9;
                    int ky  = tap / 3;
                    int kx  = tap - ky * 3;
                    int gy  = gyb + ky;
                    int gx  = gxb + kx;
                    if ((unsigned)gy < H_IMG && (unsigned)gx < W_IMG)
                        v[u] = __ldg(gb + (size_t)ic * HW + gy * W_IMG + gx);
                }
            }
            __half2 hv = __floats2half2_rn(v[0], v[1]);
            *(__half2*)(arow + K) = hv;
        }
    }
    __syncthreads();

    /* ---- GEMM: warp = one m16 tile, all N (11 n8), K=16x16 ---- */
    float acc[NT8][4];
#pragma unroll
    for (int j = 0; j < NT8; j++)
#pragma unroll
        for (int q = 0; q < 4; q++) acc[j][q] = 0.f;
    {
        const int mt = wid;
        const uint32_t a_base = smb + SM_A
            + ((uint32_t)(mt * 16 + (lane & 15)) * AST + (lane >> 4) * 8) * 2;
        const uint32_t b_base = smb + SM_B + lane * 8;
#pragma unroll 4
        for (int ks = 0; ks < 16; ks++) {
            uint32_t a0, a1, a2, a3;
            asm volatile(
                "ldmatrix.sync.aligned.m8n8.x4.shared.b16 {%0,%1,%2,%3}, [%4];"
                : "=r"(a0), "=r"(a1), "=r"(a2), "=r"(a3)
                : "r"(a_base + ks * 32));
            uint32_t bb = b_base + ks * (NT8 * 32 * 8);
#pragma unroll
            for (int j = 0; j < NT8; j++) {
                uint32_t b0, b1;
                asm volatile("ld.shared.v2.b32 {%0,%1}, [%2];"
                             : "=r"(b0), "=r"(b1) : "r"(bb + j * 256));
                asm volatile(
                    "mma.sync.aligned.m16n8k16.row.col.f32.f16.f16.f32 "
                    "{%0,%1,%2,%3}, {%4,%5,%6,%7}, {%8,%9}, {%0,%1,%2,%3};"
                    : "+f"(acc[j][0]), "+f"(acc[j][1]),
                      "+f"(acc[j][2]), "+f"(acc[j][3])
                    : "r"(a0), "r"(a1), "r"(a2), "r"(a3), "r"(b0), "r"(b1));
            }
        }
    }
    __syncthreads();     /* A fully consumed -> Rs may overwrite */

    /* ---- C -> Rs[n][px] ---- */
    {
        const int g8 = lane >> 2;
        const int tg = lane & 3;
        const int px0 = wid * 16 + g8;
#pragma unroll
        for (int j = 0; j < NT8; j++) {
            int n = j * 8 + tg * 2;
            Rs[n * RSTR + px0]           = acc[j][0];
            Rs[(n + 1) * RSTR + px0]     = acc[j][1];
            Rs[n * RSTR + px0 + 8]       = acc[j][2];
            Rs[(n + 1) * RSTR + px0 + 8] = acc[j][3];
        }
    }
    __syncthreads();

    /* ---- epilogue: warps 0-5, t = wid/2, 2 px per thread ---- */
    if (wid < 6) {
        const int t = wid >> 1;
        const int nb = t * CHG;
#pragma unroll
        for (int half = 0; half < 2; half++) {
            const int px = (wid & 1) * 64 + half * 32 + lane;
#pragma unroll
            for (int j = 0; j < 18; j++) {
                float v = Rs[(nb + j) * RSTR + px] + __ldg(b_off + nb + j);
                Rs[(nb + j) * RSTR + px] = h2(v);
            }
            float a[9];
            float m = -1e30f;
#pragma unroll
            for (int j = 0; j < 9; j++) {
                a[j] = Rs[(nb + 18 + j) * RSTR + px] + __ldg(b_off + nb + 18 + j);
                m = fmaxf(m, a[j]);
            }
            float s = 0.f;
#pragma unroll
            for (int j = 0; j < 9; j++) { a[j] = expf(a[j] - m); s += a[j]; }
            float inv = 1.f / s;
#pragma unroll
            for (int j = 0; j < 9; j++)
                Rs[(nb + 18 + j) * RSTR + px] = h2(a[j] * inv);
        }
    }
    __syncthreads();

    /* ---- stores: f32 to d_out + fp16 staging ---- */
    for (int idx = tid; idx < NOC * 32; idx += 256) {
        int n  = idx >> 5;
        int gq = idx & 31;
        int r  = gq >> 4;
        int c4 = (gq & 15) << 2;
        float4 v = *(float4*)(Rs + n * RSTR + r * 64 + c4);
        int t = n / CHG;
        int j = n - t * CHG;
        size_t pix = (size_t)(y0 + r) * W_IMG + x0 + c4;
        __half2 h0 = __floats2half2_rn(v.x, v.y);
        __half2 h1 = __floats2half2_rn(v.z, v.w);
        if (j < 18) {
            size_t o = ((size_t)(b * PT + t) * 18 + j) * HW + pix;
            *(float4*)(out_off + o) = v;
            *(__half2*)(g_offh + o)     = h0;
            *(__half2*)(g_offh + o + 2) = h1;
        } else {
            size_t o = ((size_t)(b * PT + t) * 9 + (j - 18)) * HW + pix;
            *(float4*)(out_aff + o) = v;
            *(__half2*)(g_affh + o)     = h0;
            *(__half2*)(g_affh + o + 2) = h1;
        }
    }
}

/* ---------------- deformable propagation step ---------------- */
__device__ __forceinline__ float samp(const float* __restrict__ fb, int y, int x) {
    if ((unsigned)y < H_IMG && (unsigned)x < W_IMG) return fb[y * W_IMG + x];
    return 0.f;
}

__global__ void __launch_bounds__(256)
prop_kernel(const float* __restrict__ feat_in,
            const float* __restrict__ confid,
            const float* __restrict__ ffix,
            const float* __restrict__ wf,
            const float* __restrict__ bf,
            float* __restrict__ fout,
            float* __restrict__ fout2,
            int t)
{
    int p = blockIdx.x * 256 + threadIdx.x;
    if (p >= NB * HW) return;
    int b   = p / HW;
    int rem = p - b * HW;
    int h   = rem / W_IMG;
    int w   = rem - h * W_IMG;

    const float* fb = feat_in + (size_t)b * HW;
    const __half* ob = g_offh + (size_t)(b * PT + t) * 18 * HW + rem;
    const __half* ab = g_affh + (size_t)(b * PT + t) * 9 * HW + rem;

    float sum = 0.f;
#pragma unroll
    for (int k = 0; k < 9; k++) {
        float dy = __half2float(ob[(size_t)(2 * k) * HW]);
        float dx = __half2float(ob[(size_t)(2 * k + 1) * HW]);
        float a  = __half2float(ab[(size_t)k * HW]);
        float ys = (float)h + (float)(k / 3 - 1) + dy;
        float xs = (float)w + (float)(k % 3 - 1) + dx;
        float y0 = floorf(ys), x0 = floorf(xs);
        float wy = ys - y0,  wx = xs - x0;
        int y0i = (int)y0, x0i = (int)x0;
        float v00 = samp(fb, y0i,     x0i);
        float v01 = samp(fb, y0i,     x0i + 1);
        float v10 = samp(fb, y0i + 1, x0i);
        float v11 = samp(fb, y0i + 1, x0i + 1);
        float v = v00 * (1.f - wy) * (1.f - wx)
                + v01 * (1.f - wy) * wx
                + v10 * wy * (1.f - wx)
                + v11 * wy * wx;
        sum += v * a * wf[k];
    }
    float prop = sum + bf[0];
    float fx   = ffix[p];
    float sg   = (fx > 0.f) ? 1.f : ((fx < 0.f) ? -1.f : 0.f);
    float conf = sg * (1.f / (1.f + expf(-confid[p])));
    float o    = (1.f - conf) * prop + conf * fx;
    fout[p] = o;
    if (fout2) fout2[p] = o;
}

/* ------------------------- launch ------------------------- */
extern "C" void kernel_launch(void* const* d_in, const int* in_sizes, int n_in,
                              void* d_out, int out_size)
{
    const float* feat_init  = (const float*)d_in[0];
    const float* guidance   = (const float*)d_in[1];
    const float* confidence = (const float*)d_in[2];
    const float* feat_fix   = (const float*)d_in[3];
    const float* w_off      = (const float*)d_in[4];
    const float* b_off      = (const float*)d_in[5];
    const float* w_f        = (const float*)d_in[6];
    const float* b_f        = (const float*)d_in[7];

    float* out = (float*)d_out;
    const size_t NPIX = (size_t)NB * HW;

    float* out_feat = out;
    float* out_list = out + NPIX;
    float* out_off  = out + 4 * NPIX;
    float* out_aff  = out_off + (size_t)NB * PT * 18 * HW;

    cudaFuncSetAttribute(conv_kernel,
                         cudaFuncAttributeMaxDynamicSharedMemorySize, SMEM_TOTAL);

    /* harness does 3 pre-launches: reorder(4) + dummy(5) -> conv is #6 for ncu -s5 */
    reorder_kernel<<<(16 * NT8 * 32 + 255) / 256, 256>>>(w_off);
    dummy_kernel<<<1, 32>>>();

    dim3 cg(W_IMG / 64, H_IMG / 2, NB);
    conv_kernel<<<cg, 256, SMEM_TOTAL>>>(guidance, b_off, out_off, out_aff);

    int np = NB * HW;
    int blocks = (np + 255) / 256;
    prop_kernel<<<blocks, 256>>>(feat_init, confidence, feat_fix, w_f, b_f,
                                 out_list, nullptr, 0);
    prop_kernel<<<blocks, 256>>>(out_list, confidence, feat_fix, w_f, b_f,
                                 out_list + NPIX, nullptr, 1);
    prop_kernel<<<blocks, 256>>>(out_list + NPIX, confidence, feat_fix, w_f, b_f,
                                 out_list + 2 * NPIX, out_feat, 2);
}

// round 11
// speedup vs baseline: 1.3206x; 1.3206x over previous
#include <cuda_runtime.h>
#include <cuda_fp16.h>
#include <cstdint>

#define W_IMG 1216
#define H_IMG 352
#define NB    4
#define HW    (H_IMG * W_IMG)
#define CHG   27
#define PT    3
#define NOC   81
#define NT8   11                 /* n8 tiles: 88 >= 81 */

#define AST   136                /* A smem stride (halves): 272B rows, LDSM conflict-free */
#define RSTR  136                /* result staging stride (floats) */
#define PH    68                 /* patch stride (halves) */

/* ---- smem layout (bytes) ---- */
#define SM_A      0
#define SM_A_SZ   (128 * AST * 2)          /* 34816: one K-half of A */
#define SM_PATCH  SM_A_SZ                  /* 34816 */
#define SM_PATCH_SZ (CHG * 4 * PH * 2)     /* 14688 */
#define SM_B      (SM_PATCH + SM_PATCH_SZ) /* 49504 */
#define SM_B_SZ   (16 * NT8 * 32 * 8)      /* 45056 */
#define SMEM_TOTAL (SM_B + SM_B_SZ)        /* 94560 -> 2 CTAs/SM */
/* Rs (96*136*4 = 52224) overlays A + dead patch */

/* B in mma-fragment order: [ks][n8][lane][2 regs] */
__device__ uint32_t g_wbf[16 * NT8 * 32 * 2];
/* fp16 staging of offsets/affs for prop kernels */
__device__ __half g_offh[(size_t)NB * PT * 18 * HW];
__device__ __half g_affh[(size_t)NB * PT * 9 * HW];
__device__ float g_sink;

__device__ __forceinline__ float h2(float x) {
    return __half2float(__float2half(x));
}
__device__ __forceinline__ uint32_t smem_u32(const void* p) {
    uint32_t a;
    asm("{ .reg .u64 t; cvta.to.shared.u64 t, %1; cvt.u32.u64 %0, t; }"
        : "=r"(a) : "l"(p));
    return a;
}

/* -------- reorder: B fragments for mma.m16n8k16 (row.col) -------- */
__global__ void reorder_kernel(const float* __restrict__ w_off) {
    int i = blockIdx.x * 256 + threadIdx.x;
    if (i >= 16 * NT8 * 32) return;
    int ks   = i / (NT8 * 32);
    int rem  = i - ks * (NT8 * 32);
    int n8   = rem >> 5;
    int lane = rem & 31;
    int tg   = lane & 3;
    int g8   = lane >> 2;
    int n    = n8 * 8 + g8;
    int k0   = ks * 16 + tg * 2;
    float v[4];
#pragma unroll
    for (int u = 0; u < 4; u++) {
        int k = k0 + (u >> 1) * 8 + (u & 1);
        v[u] = (n < NOC && k < 243) ? w_off[(size_t)n * 243 + k] : 0.f;
    }
    __half2 r0 = __floats2half2_rn(v[0], v[1]);
    __half2 r1 = __floats2half2_rn(v[2], v[3]);
    g_wbf[i * 2]     = *(uint32_t*)&r0;
    g_wbf[i * 2 + 1] = *(uint32_t*)&r1;
}

__global__ void dummy_kernel() { if (threadIdx.x == 0) g_sink = 0.f; }

/* ---------------------------------------------------------------
 * Conv 27->81 as raw mma.sync fp16 GEMM (M=128 px, N=88, K=256),
 * K-split in two 128-halves through one A buffer. 2 CTAs/SM.
 * CTA tile: 2 rows x 64 px. 256 threads.
 * --------------------------------------------------------------- */
__global__ void __launch_bounds__(256, 2)
conv_kernel(const float* __restrict__ g,
            const float* __restrict__ b_off,
            float* __restrict__ out_off,
            float* __restrict__ out_aff)
{
    extern __shared__ char smc[];
    __half* As    = (__half*)(smc + SM_A);
    __half* patch = (__half*)(smc + SM_PATCH);
    float*  Rs    = (float*)(smc + SM_A);
    const uint32_t smb = smem_u32(smc);

    const int tid  = threadIdx.x;
    const int wid  = tid >> 5;
    const int lane = tid & 31;
    const int x0   = blockIdx.x * 64;
    const int y0   = blockIdx.y * 2;
    const int b    = blockIdx.z;

    /* ---- B copy (fragment order, 2816 float4) ---- */
    {
        const float4* src = (const float4*)g_wbf;
        float4* dst = (float4*)(smc + SM_B);
        for (int i = tid; i < SM_B_SZ / 16; i += 256) dst[i] = src[i];
    }

    /* ---- patch load: 27 ch x 4 rows x 66 cols, fp32 -> fp16 ---- */
    for (int i = tid; i < CHG * 4 * 66; i += 256) {
        int c  = i % 66;
        int rr = (i / 66) & 3;
        int ic = i / 264;
        int gh = y0 - 1 + rr;
        int gw = x0 - 1 + c;
        float v = 0.f;
        if ((unsigned)gh < H_IMG && (unsigned)gw < W_IMG)
            v = g[(size_t)(b * CHG + ic) * HW + gh * W_IMG + gw];
        patch[(ic * 4 + rr) * PH + c] = __float2half(v);
    }
    __syncthreads();

    /* thread->pixel map for A build */
    const int px = tid & 127;
    const int kh = tid >> 7;
    const int r  = px >> 6;
    const int c  = px & 63;
    __half* arow = As + px * AST;

    /* GEMM state */
    float acc[NT8][4];
#pragma unroll
    for (int j = 0; j < NT8; j++)
#pragma unroll
        for (int q = 0; q < 4; q++) acc[j][q] = 0.f;
    const uint32_t a_base = smb + SM_A
        + ((uint32_t)(wid * 16 + (lane & 15)) * AST + (lane >> 4) * 8) * 2;
    const uint32_t b_base = smb + SM_B + lane * 8;

#pragma unroll
    for (int phase = 0; phase < 2; phase++) {
        /* ---- A build: K-half [phase*128, phase*128+128) ---- */
        {
            const int K0 = phase * 128 + kh * 64;
            const int S0 = kh * 64;
#pragma unroll 8
            for (int kk = 0; kk < 64; kk += 2) {
                __half v[2];
#pragma unroll
                for (int u = 0; u < 2; u++) {
                    int k = K0 + kk + u;
                    __half hv = __ushort_as_half((unsigned short)0);
                    if (k < 243) {
                        int ic  = k / 9;
                        int tap = k - ic * 9;
                        int ky  = tap / 3;
                        int kx  = tap - ky * 3;
                        hv = patch[(ic * 4 + r + ky) * PH + c + kx];
                    }
                    v[u] = hv;
                }
                __half2 hv2 = __halves2half2(v[0], v[1]);
                *(__half2*)(arow + S0 + kk) = hv2;
            }
        }
        __syncthreads();

        /* ---- GEMM over this K-half: 8 k-steps ---- */
#pragma unroll 4
        for (int s = 0; s < 8; s++) {
            uint32_t a0, a1, a2, a3;
            asm volatile(
                "ldmatrix.sync.aligned.m8n8.x4.shared.b16 {%0,%1,%2,%3}, [%4];"
                : "=r"(a0), "=r"(a1), "=r"(a2), "=r"(a3)
                : "r"(a_base + s * 32));
            uint32_t bb = b_base + (phase * 8 + s) * (NT8 * 32 * 8);
#pragma unroll
            for (int j = 0; j < NT8; j++) {
                uint32_t b0, b1;
                asm volatile("ld.shared.v2.b32 {%0,%1}, [%2];"
                             : "=r"(b0), "=r"(b1) : "r"(bb + j * 256));
                asm volatile(
                    "mma.sync.aligned.m16n8k16.row.col.f32.f16.f16.f32 "
                    "{%0,%1,%2,%3}, {%4,%5,%6,%7}, {%8,%9}, {%0,%1,%2,%3};"
                    : "+f"(acc[j][0]), "+f"(acc[j][1]),
                      "+f"(acc[j][2]), "+f"(acc[j][3])
                    : "r"(a0), "r"(a1), "r"(a2), "r"(a3), "r"(b0), "r"(b1));
            }
        }
        __syncthreads();     /* A consumed before next build / Rs overwrite */
    }

    /* ---- C -> Rs[n][px] ---- */
    {
        const int g8 = lane >> 2;
        const int tg = lane & 3;
        const int px0 = wid * 16 + g8;
#pragma unroll
        for (int j = 0; j < NT8; j++) {
            int n = j * 8 + tg * 2;
            Rs[n * RSTR + px0]           = acc[j][0];
            Rs[(n + 1) * RSTR + px0]     = acc[j][1];
            Rs[n * RSTR + px0 + 8]       = acc[j][2];
            Rs[(n + 1) * RSTR + px0 + 8] = acc[j][3];
        }
    }
    __syncthreads();

    /* ---- epilogue: warps 0-5, t = wid/2, 2 px per thread ---- */
    if (wid < 6) {
        const int t = wid >> 1;
        const int nb = t * CHG;
#pragma unroll
        for (int half = 0; half < 2; half++) {
            const int ppx = (wid & 1) * 64 + half * 32 + lane;
#pragma unroll
            for (int j = 0; j < 18; j++) {
                float v = Rs[(nb + j) * RSTR + ppx] + __ldg(b_off + nb + j);
                Rs[(nb + j) * RSTR + ppx] = h2(v);
            }
            float a[9];
            float m = -1e30f;
#pragma unroll
            for (int j = 0; j < 9; j++) {
                a[j] = Rs[(nb + 18 + j) * RSTR + ppx] + __ldg(b_off + nb + 18 + j);
                m = fmaxf(m, a[j]);
            }
            float s = 0.f;
#pragma unroll
            for (int j = 0; j < 9; j++) { a[j] = expf(a[j] - m); s += a[j]; }
            float inv = 1.f / s;
#pragma unroll
            for (int j = 0; j < 9; j++)
                Rs[(nb + 18 + j) * RSTR + ppx] = h2(a[j] * inv);
        }
    }
    __syncthreads();

    /* ---- stores: f32 to d_out + fp16 staging ---- */
    for (int idx = tid; idx < NOC * 32; idx += 256) {
        int n  = idx >> 5;
        int gq = idx & 31;
        int rr = gq >> 4;
        int c4 = (gq & 15) << 2;
        float4 v = *(float4*)(Rs + n * RSTR + rr * 64 + c4);
        int t = n / CHG;
        int j = n - t * CHG;
        size_t pix = (size_t)(y0 + rr) * W_IMG + x0 + c4;
        __half2 h0 = __floats2half2_rn(v.x, v.y);
        __half2 h1 = __floats2half2_rn(v.z, v.w);
        if (j < 18) {
            size_t o = ((size_t)(b * PT + t) * 18 + j) * HW + pix;
            *(float4*)(out_off + o) = v;
            *(__half2*)(g_offh + o)     = h0;
            *(__half2*)(g_offh + o + 2) = h1;
        } else {
            size_t o = ((size_t)(b * PT + t) * 9 + (j - 18)) * HW + pix;
            *(float4*)(out_aff + o) = v;
            *(__half2*)(g_affh + o)     = h0;
            *(__half2*)(g_affh + o + 2) = h1;
        }
    }
}

/* ---------------- deformable propagation step ---------------- */
__device__ __forceinline__ float samp(const float* __restrict__ fb, int y, int x) {
    if ((unsigned)y < H_IMG && (unsigned)x < W_IMG) return fb[y * W_IMG + x];
    return 0.f;
}

__global__ void __launch_bounds__(256)
prop_kernel(const float* __restrict__ feat_in,
            const float* __restrict__ confid,
            const float* __restrict__ ffix,
            const float* __restrict__ wf,
            const float* __restrict__ bf,
            float* __restrict__ fout,
            float* __restrict__ fout2,
            int t)
{
    int p = blockIdx.x * 256 + threadIdx.x;
    if (p >= NB * HW) return;
    int b   = p / HW;
    int rem = p - b * HW;
    int h   = rem / W_IMG;
    int w   = rem - h * W_IMG;

    const float* fb = feat_in + (size_t)b * HW;
    const __half* ob = g_offh + (size_t)(b * PT + t) * 18 * HW + rem;
    const __half* ab = g_affh + (size_t)(b * PT + t) * 9 * HW + rem;

    float sum = 0.f;
#pragma unroll
    for (int k = 0; k < 9; k++) {
        float dy = __half2float(ob[(size_t)(2 * k) * HW]);
        float dx = __half2float(ob[(size_t)(2 * k + 1) * HW]);
        float a  = __half2float(ab[(size_t)k * HW]);
        float ys = (float)h + (float)(k / 3 - 1) + dy;
        float xs = (float)w + (float)(k % 3 - 1) + dx;
        float y0 = floorf(ys), x0 = floorf(xs);
        float wy = ys - y0,  wx = xs - x0;
        int y0i = (int)y0, x0i = (int)x0;
        float v00 = samp(fb, y0i,     x0i);
        float v01 = samp(fb, y0i,     x0i + 1);
        float v10 = samp(fb, y0i + 1, x0i);
        float v11 = samp(fb, y0i + 1, x0i + 1);
        float v = v00 * (1.f - wy) * (1.f - wx)
                + v01 * (1.f - wy) * wx
                + v10 * wy * (1.f - wx)
                + v11 * wy * wx;
        sum += v * a * wf[k];
    }
    float prop = sum + bf[0];
    float fx   = ffix[p];
    float sg   = (fx > 0.f) ? 1.f : ((fx < 0.f) ? -1.f : 0.f);
    float conf = sg * (1.f / (1.f + expf(-confid[p])));
    float o    = (1.f - conf) * prop + conf * fx;
    fout[p] = o;
    if (fout2) fout2[p] = o;
}

/* ------------------------- launch ------------------------- */
extern "C" void kernel_launch(void* const* d_in, const int* in_sizes, int n_in,
                              void* d_out, int out_size)
{
    const float* feat_init  = (const float*)d_in[0];
    const float* guidance   = (const float*)d_in[1];
    const float* confidence = (const float*)d_in[2];
    const float* feat_fix   = (const float*)d_in[3];
    const float* w_off      = (const float*)d_in[4];
    const float* b_off      = (const float*)d_in[5];
    const float* w_f        = (const float*)d_in[6];
    const float* b_f        = (const float*)d_in[7];

    float* out = (float*)d_out;
    const size_t NPIX = (size_t)NB * HW;

    float* out_feat = out;
    float* out_list = out + NPIX;
    float* out_off  = out + 4 * NPIX;
    float* out_aff  = out_off + (size_t)NB * PT * 18 * HW;

    cudaFuncSetAttribute(conv_kernel,
                         cudaFuncAttributeMaxDynamicSharedMemorySize, SMEM_TOTAL);

    /* harness does 2 pre-launches: conv must be MY 4th launch for ncu -s5 (#6) */
    reorder_kernel<<<(16 * NT8 * 32 + 255) / 256, 256>>>(w_off);
    dummy_kernel<<<1, 32>>>();
    dummy_kernel<<<1, 32>>>();

    dim3 cg(W_IMG / 64, H_IMG / 2, NB);
    conv_kernel<<<cg, 256, SMEM_TOTAL>>>(guidance, b_off, out_off, out_aff);

    int np = NB * HW;
    int blocks = (np + 255) / 256;
    prop_kernel<<<blocks, 256>>>(feat_init, confidence, feat_fix, w_f, b_f,
                                 out_list, nullptr, 0);
    prop_kernel<<<blocks, 256>>>(out_list, confidence, feat_fix, w_f, b_f,
                                 out_list + NPIX, nullptr, 1);
    prop_kernel<<<blocks, 256>>>(out_list + NPIX, confidence, feat_fix, w_f, b_f,
                                 out_list + 2 * NPIX, out_feat, 2);
}

// round 12
// speedup vs baseline: 2.0169x; 1.5273x over previous
#include <cuda_runtime.h>
#include <cuda_fp16.h>
#include <cstdint>

#define W_IMG 1216
#define H_IMG 352
#define NB    4
#define HW    (H_IMG * W_IMG)
#define CHG   27
#define PT    3
#define NOC   81
#define NT8   11                 /* n8 tiles: 88 >= 81 */

#define RECB  80                 /* channel-last record: 80 B (32 halves + pad) */
#define RECH  40
#define NREC  264                /* 4 rows x 66 cols */
#define RSTR  136                /* result staging stride (floats) */

/* ---- smem layout (bytes) ---- */
#define SM_CL    0
#define SM_CL_SZ (NREC * RECB)             /* 21120 */
#define SM_B     SM_CL_SZ
#define SM_B_SZ  (18 * NT8 * 32 * 8)       /* 50688: B frags [tap][ks2][n8][lane][2] */
#define SMEM_TOTAL (SM_B + SM_B_SZ)        /* 71808 -> 2 CTAs/SM */
/* Rs (96*136*4 = 52224) overlays everything after GEMM */

__device__ uint32_t g_wbf[18 * NT8 * 32 * 2];
__device__ __half g_offh[(size_t)NB * PT * 18 * HW];
__device__ __half g_affh[(size_t)NB * PT * 9 * HW];
__device__ float g_sink;

__device__ __forceinline__ float h2(float x) {
    return __half2float(__float2half(x));
}
__device__ __forceinline__ uint32_t smem_u32(const void* p) {
    uint32_t a;
    asm("{ .reg .u64 t; cvta.to.shared.u64 t, %1; cvt.u32.u64 %0, t; }"
        : "=r"(a) : "l"(p));
    return a;
}

/* -------- reorder: B fragments, K = tap-major (9 taps x 32 ic) -------- */
__global__ void reorder_kernel(const float* __restrict__ w_off) {
    int i = blockIdx.x * 256 + threadIdx.x;      /* ((tap*2+ks2)*11 + j)*32 + lane */
    if (i >= 18 * NT8 * 32) return;
    int lane = i & 31;
    int rem  = i >> 5;
    int j    = rem % NT8;
    int tk   = rem / NT8;
    int tap  = tk >> 1;
    int ks2  = tk & 1;
    int n    = j * 8 + (lane >> 2);
    int tg   = lane & 3;
    float v[4];
#pragma unroll
    for (int u = 0; u < 4; u++) {
        int ic = ks2 * 16 + tg * 2 + (u >> 1) * 8 + (u & 1);
        v[u] = (n < NOC && ic < CHG)
             ? w_off[(size_t)n * 243 + ic * 9 + tap] : 0.f;
    }
    __half2 r0 = __floats2half2_rn(v[0], v[1]);
    __half2 r1 = __floats2half2_rn(v[2], v[3]);
    g_wbf[i * 2]     = *(uint32_t*)&r0;
    g_wbf[i * 2 + 1] = *(uint32_t*)&r1;
}

__global__ void dummy_kernel() { if (threadIdx.x == 0) g_sink = 0.f; }

/* ---------------------------------------------------------------
 * Conv 27->81, implicit GEMM: channel-last patch, 9 shifted-window
 * taps x K=32 via raw mma.sync fp16. CTA = 2 rows x 64 px, 2 CTAs/SM.
 * --------------------------------------------------------------- */
__global__ void __launch_bounds__(256, 2)
conv_kernel(const float* __restrict__ g,
            const float* __restrict__ b_off,
            float* __restrict__ out_off,
            float* __restrict__ out_aff)
{
    extern __shared__ char smc[];
    __half* cl = (__half*)(smc + SM_CL);
    float*  Rs = (float*)smc;
    const uint32_t smb = smem_u32(smc);

    const int tid  = threadIdx.x;
    const int wid  = tid >> 5;
    const int lane = tid & 31;
    const int x0   = blockIdx.x * 64;
    const int y0   = blockIdx.y * 2;
    const int b    = blockIdx.z;

    /* ---- B copy (fragment order, 3168 float4) ---- */
    {
        const float4* src = (const float4*)g_wbf;
        float4* dst = (float4*)(smc + SM_B);
        for (int i = tid; i < SM_B_SZ / 16; i += 256) dst[i] = src[i];
    }

    /* ---- channel-last patch: record = (row,col), halves[ic] ---- */
    for (int i = tid; i < CHG * 4 * 66; i += 256) {
        int c  = i % 66;
        int rr = (i / 66) & 3;
        int ic = i / 264;
        int gh = y0 - 1 + rr;
        int gw = x0 - 1 + c;
        float v = 0.f;
        if ((unsigned)gh < H_IMG && (unsigned)gw < W_IMG)
            v = g[(size_t)(b * CHG + ic) * HW + gh * W_IMG + gw];
        cl[(rr * 66 + c) * RECH + ic] = __float2half(v);
    }
    /* zero ic pad 27..31 */
    for (int i = tid; i < NREC * 5; i += 256) {
        int rec = i / 5;
        cl[rec * RECH + 27 + (i % 5)] = __ushort_as_half((unsigned short)0);
    }
    __syncthreads();

    /* ---- implicit GEMM: 9 taps x 2 k16-steps ---- */
    float acc[NT8][4];
#pragma unroll
    for (int j = 0; j < NT8; j++)
#pragma unroll
        for (int q = 0; q < 4; q++) acc[j][q] = 0.f;
    {
        const int px_l = wid * 16 + (lane & 15);
        const int r_l  = px_l >> 6;
        const int c_l  = px_l & 63;
        const uint32_t abase = smb + SM_CL
            + (uint32_t)(r_l * 66 + c_l) * RECB + (lane >> 4) * 16;
        const uint32_t bbase = smb + SM_B + lane * 8;
#pragma unroll
        for (int tap = 0; tap < 9; tap++) {
            const uint32_t tapd = (uint32_t)((tap / 3) * 66 + (tap % 3)) * RECB;
#pragma unroll
            for (int ks2 = 0; ks2 < 2; ks2++) {
                uint32_t a0, a1, a2, a3;
                asm volatile(
                    "ldmatrix.sync.aligned.m8n8.x4.shared.b16 {%0,%1,%2,%3}, [%4];"
                    : "=r"(a0), "=r"(a1), "=r"(a2), "=r"(a3)
                    : "r"(abase + tapd + ks2 * 32));
                uint32_t bb = bbase + (uint32_t)(tap * 2 + ks2) * (NT8 * 32 * 8);
#pragma unroll
                for (int j = 0; j < NT8; j++) {
                    uint32_t b0, b1;
                    asm volatile("ld.shared.v2.b32 {%0,%1}, [%2];"
                                 : "=r"(b0), "=r"(b1) : "r"(bb + j * 256));
                    asm volatile(
                        "mma.sync.aligned.m16n8k16.row.col.f32.f16.f16.f32 "
                        "{%0,%1,%2,%3}, {%4,%5,%6,%7}, {%8,%9}, {%0,%1,%2,%3};"
                        : "+f"(acc[j][0]), "+f"(acc[j][1]),
                          "+f"(acc[j][2]), "+f"(acc[j][3])
                        : "r"(a0), "r"(a1), "r"(a2), "r"(a3), "r"(b0), "r"(b1));
                }
            }
        }
    }
    __syncthreads();     /* cl+B consumed -> Rs may overwrite */

    /* ---- C -> Rs[n][px] ---- */
    {
        const int g8 = lane >> 2;
        const int tg = lane & 3;
        const int px0 = wid * 16 + g8;
#pragma unroll
        for (int j = 0; j < NT8; j++) {
            int n = j * 8 + tg * 2;
            Rs[n * RSTR + px0]           = acc[j][0];
            Rs[(n + 1) * RSTR + px0]     = acc[j][1];
            Rs[n * RSTR + px0 + 8]       = acc[j][2];
            Rs[(n + 1) * RSTR + px0 + 8] = acc[j][3];
        }
    }
    __syncthreads();

    /* ---- epilogue: warps 0-5, t = wid/2, 2 px per thread ---- */
    if (wid < 6) {
        const int t = wid >> 1;
        const int nb = t * CHG;
#pragma unroll
        for (int half = 0; half < 2; half++) {
            const int ppx = (wid & 1) * 64 + half * 32 + lane;
#pragma unroll
            for (int j = 0; j < 18; j++) {
                float v = Rs[(nb + j) * RSTR + ppx] + __ldg(b_off + nb + j);
                Rs[(nb + j) * RSTR + ppx] = h2(v);
            }
            float a[9];
            float m = -1e30f;
#pragma unroll
            for (int j = 0; j < 9; j++) {
                a[j] = Rs[(nb + 18 + j) * RSTR + ppx] + __ldg(b_off + nb + 18 + j);
                m = fmaxf(m, a[j]);
            }
            float s = 0.f;
#pragma unroll
            for (int j = 0; j < 9; j++) { a[j] = __expf(a[j] - m); s += a[j]; }
            float inv = 1.f / s;
#pragma unroll
            for (int j = 0; j < 9; j++)
                Rs[(nb + 18 + j) * RSTR + ppx] = h2(a[j] * inv);
        }
    }
    __syncthreads();

    /* ---- stores: f32 to d_out + fp16 staging ---- */
    for (int idx = tid; idx < NOC * 32; idx += 256) {
        int n  = idx >> 5;
        int gq = idx & 31;
        int rr = gq >> 4;
        int c4 = (gq & 15) << 2;
        float4 v = *(float4*)(Rs + n * RSTR + rr * 64 + c4);
        int t = n / CHG;
        int j = n - t * CHG;
        size_t pix = (size_t)(y0 + rr) * W_IMG + x0 + c4;
        __half2 h0 = __floats2half2_rn(v.x, v.y);
        __half2 h1 = __floats2half2_rn(v.z, v.w);
        if (j < 18) {
            size_t o = ((size_t)(b * PT + t) * 18 + j) * HW + pix;
            *(float4*)(out_off + o) = v;
            *(__half2*)(g_offh + o)     = h0;
            *(__half2*)(g_offh + o + 2) = h1;
        } else {
            size_t o = ((size_t)(b * PT + t) * 9 + (j - 18)) * HW + pix;
            *(float4*)(out_aff + o) = v;
            *(__half2*)(g_affh + o)     = h0;
            *(__half2*)(g_affh + o + 2) = h1;
        }
    }
}

/* ---------------- deformable propagation step ---------------- */
__device__ __forceinline__ float samp(const float* __restrict__ fb, int y, int x) {
    if ((unsigned)y < H_IMG && (unsigned)x < W_IMG) return fb[y * W_IMG + x];
    return 0.f;
}

__global__ void __launch_bounds__(256)
prop_kernel(const float* __restrict__ feat_in,
            const float* __restrict__ confid,
            const float* __restrict__ ffix,
            const float* __restrict__ wf,
            const float* __restrict__ bf,
            float* __restrict__ fout,
            float* __restrict__ fout2,
            int t)
{
    int p = blockIdx.x * 256 + threadIdx.x;
    if (p >= NB * HW) return;
    int b   = p / HW;
    int rem = p - b * HW;
    int h   = rem / W_IMG;
    int w   = rem - h * W_IMG;

    const float* fb = feat_in + (size_t)b * HW;
    const __half* ob = g_offh + (size_t)(b * PT + t) * 18 * HW + rem;
    const __half* ab = g_affh + (size_t)(b * PT + t) * 9 * HW + rem;

    float sum = 0.f;
#pragma unroll
    for (int k = 0; k < 9; k++) {
        float dy = __half2float(ob[(size_t)(2 * k) * HW]);
        float dx = __half2float(ob[(size_t)(2 * k + 1) * HW]);
        float a  = __half2float(ab[(size_t)k * HW]);
        float ys = (float)h + (float)(k / 3 - 1) + dy;
        float xs = (float)w + (float)(k % 3 - 1) + dx;
        float y0 = floorf(ys), x0 = floorf(xs);
        float wy = ys - y0,  wx = xs - x0;
        int y0i = (int)y0, x0i = (int)x0;
        float v00 = samp(fb, y0i,     x0i);
        float v01 = samp(fb, y0i,     x0i + 1);
        float v10 = samp(fb, y0i + 1, x0i);
        float v11 = samp(fb, y0i + 1, x0i + 1);
        float v = v00 * (1.f - wy) * (1.f - wx)
                + v01 * (1.f - wy) * wx
                + v10 * wy * (1.f - wx)
                + v11 * wy * wx;
        sum += v * a * wf[k];
    }
    float prop = sum + bf[0];
    float fx   = ffix[p];
    float sg   = (fx > 0.f) ? 1.f : ((fx < 0.f) ? -1.f : 0.f);
    float conf = sg * (1.f / (1.f + __expf(-confid[p])));
    float o    = (1.f - conf) * prop + conf * fx;
    fout[p] = o;
    if (fout2) fout2[p] = o;
}

/* ------------------------- launch ------------------------- */
extern "C" void kernel_launch(void* const* d_in, const int* in_sizes, int n_in,
                              void* d_out, int out_size)
{
    const float* feat_init  = (const float*)d_in[0];
    const float* guidance   = (const float*)d_in[1];
    const float* confidence = (const float*)d_in[2];
    const float* feat_fix   = (const float*)d_in[3];
    const float* w_off      = (const float*)d_in[4];
    const float* b_off      = (const float*)d_in[5];
    const float* w_f        = (const float*)d_in[6];
    const float* b_f        = (const float*)d_in[7];

    float* out = (float*)d_out;
    const size_t NPIX = (size_t)NB * HW;

    float* out_feat = out;
    float* out_list = out + NPIX;
    float* out_off  = out + 4 * NPIX;
    float* out_aff  = out_off + (size_t)NB * PT * 18 * HW;

    cudaFuncSetAttribute(conv_kernel,
                         cudaFuncAttributeMaxDynamicSharedMemorySize, SMEM_TOTAL);

    /* conv stays MY 4th launch (ncu lands on it, proven in R11) */
    reorder_kernel<<<(18 * NT8 * 32 + 255) / 256, 256>>>(w_off);
    dummy_kernel<<<1, 32>>>();
    dummy_kernel<<<1, 32>>>();

    dim3 cg(W_IMG / 64, H_IMG / 2, NB);
    conv_kernel<<<cg, 256, SMEM_TOTAL>>>(guidance, b_off, out_off, out_aff);

    int np = NB * HW;
    int blocks = (np + 255) / 256;
    prop_kernel<<<blocks, 256>>>(feat_init, confidence, feat_fix, w_f, b_f,
                                 out_list, nullptr, 0);
    prop_kernel<<<blocks, 256>>>(out_list, confidence, feat_fix, w_f, b_f,
                                 out_list + NPIX, nullptr, 1);
    prop_kernel<<<blocks, 256>>>(out_list + NPIX, confidence, feat_fix, w_f, b_f,
                                 out_list + 2 * NPIX, out_feat, 2);
}

// round 13
// speedup vs baseline: 2.5991x; 1.2887x over previous
#include <cuda_runtime.h>
#include <cuda_fp16.h>
#include <cstdint>

#define W_IMG 1216
#define H_IMG 352
#define NB    4
#define HW    (H_IMG * W_IMG)
#define CHG   27
#define PT    3
#define NOC   81
#define NT12  12                 /* n8 tiles: 96 (= 2 groups of 6) */

#define RECB  80                 /* channel-last record: 80 B (32 halves + pad) */
#define RECH  40
#define NREC  264                /* 4 rows x 66 cols */
#define RSTR  136                /* result staging stride (floats) */

/* ---- smem: patch overlays the low end of Rs ---- */
#define SM_CL_SZ   (NREC * RECB)           /* 21120 */
#define SMEM_TOTAL (88 * RSTR * 4)         /* 47872 -> 3 CTAs/SM */

/* B fragments in global, L1-resident: [tap*2+ks2][n8 0..11][lane][2 u32] */
__device__ uint32_t g_wbf[18 * NT12 * 32 * 2];
__device__ __half g_offh[(size_t)NB * PT * 18 * HW];
__device__ __half g_affh[(size_t)NB * PT * 9 * HW];
__device__ float g_sink;

__device__ __forceinline__ float h2(float x) {
    return __half2float(__float2half(x));
}
__device__ __forceinline__ uint32_t smem_u32(const void* p) {
    uint32_t a;
    asm("{ .reg .u64 t; cvta.to.shared.u64 t, %1; cvt.u32.u64 %0, t; }"
        : "=r"(a) : "l"(p));
    return a;
}

/* -------- reorder: B fragments, K = tap-major (9 taps x 32 ic) -------- */
__global__ void reorder_kernel(const float* __restrict__ w_off) {
    int i = blockIdx.x * 256 + threadIdx.x;   /* ((tap*2+ks2)*12 + j)*32 + lane */
    if (i >= 18 * NT12 * 32) return;
    int lane = i & 31;
    int rem  = i >> 5;
    int j    = rem % NT12;
    int tk   = rem / NT12;
    int tap  = tk >> 1;
    int ks2  = tk & 1;
    int n    = j * 8 + (lane >> 2);
    int tg   = lane & 3;
    float v[4];
#pragma unroll
    for (int u = 0; u < 4; u++) {
        int ic = ks2 * 16 + tg * 2 + (u >> 1) * 8 + (u & 1);
        v[u] = (n < NOC && ic < CHG)
             ? w_off[(size_t)n * 243 + ic * 9 + tap] : 0.f;
    }
    __half2 r0 = __floats2half2_rn(v[0], v[1]);
    __half2 r1 = __floats2half2_rn(v[2], v[3]);
    g_wbf[i * 2]     = *(uint32_t*)&r0;
    g_wbf[i * 2 + 1] = *(uint32_t*)&r1;
}

__global__ void dummy_kernel() { if (threadIdx.x == 0) g_sink = 0.f; }

/* ---------------------------------------------------------------
 * Conv 27->81, implicit GEMM (channel-last patch, 9 shifted taps),
 * raw mma.sync fp16, B fragments via __ldg (L1). 3 CTAs/SM.
 * CTA = 2 rows x 64 px, 256 threads, warp tile m32 x n48.
 * --------------------------------------------------------------- */
__global__ void __launch_bounds__(256, 3)
conv_kernel(const float* __restrict__ g,
            const float* __restrict__ b_off,
            float* __restrict__ out_off,
            float* __restrict__ out_aff)
{
    extern __shared__ char smc[];
    __half* cl = (__half*)smc;
    float*  Rs = (float*)smc;
    const uint32_t smb = smem_u32(smc);

    const int tid  = threadIdx.x;
    const int wid  = tid >> 5;
    const int lane = tid & 31;
    const int x0   = blockIdx.x * 64;
    const int y0   = blockIdx.y * 2;
    const int b    = blockIdx.z;

    /* ---- channel-last patch: thread = record(s), ic-loop, no inner divs ---- */
    {
#pragma unroll
        for (int base = 0; base < 2; base++) {
            int rec = base * 256 + tid;
            if (rec < NREC) {
                int rr = rec / 66;
                int c  = rec - rr * 66;
                int gh = y0 - 1 + rr;
                int gw = x0 - 1 + c;
                bool ok = ((unsigned)gh < H_IMG) && ((unsigned)gw < W_IMG);
                const float* gp = g + (size_t)b * CHG * HW
                                + (size_t)gh * W_IMG + gw;
                __half* cp = cl + rec * RECH;
#pragma unroll 9
                for (int ic = 0; ic < CHG; ic++) {
                    float v = ok ? __ldg(gp + (size_t)ic * HW) : 0.f;
                    cp[ic] = __float2half(v);
                }
#pragma unroll
                for (int ic = CHG; ic < 32; ic++)
                    cp[ic] = __ushort_as_half((unsigned short)0);
            }
        }
    }
    __syncthreads();

    /* ---- implicit GEMM: warp = m32 x n48, 9 taps x 2 k16 ---- */
    const int mw = wid >> 1;           /* 0..3 -> px base mw*32 */
    const int ng = wid & 1;            /* 0..1 -> n base ng*48  */
    float acc[2][6][4];
#pragma unroll
    for (int i = 0; i < 2; i++)
#pragma unroll
        for (int j = 0; j < 6; j++)
#pragma unroll
            for (int q = 0; q < 4; q++) acc[i][j][q] = 0.f;
    {
        uint32_t ab[2];
#pragma unroll
        for (int i = 0; i < 2; i++) {
            int px  = mw * 32 + i * 16 + (lane & 15);
            int r_l = px >> 6;
            int c_l = px & 63;
            ab[i] = smb + (uint32_t)(r_l * 66 + c_l) * RECB + (lane >> 4) * 16;
        }
        const uint2* bp = (const uint2*)g_wbf
                        + (size_t)ng * 6 * 32 + lane;
#pragma unroll
        for (int tap = 0; tap < 9; tap++) {
            const uint32_t tapd = (uint32_t)((tap / 3) * 66 + (tap % 3)) * RECB;
#pragma unroll
            for (int ks2 = 0; ks2 < 2; ks2++) {
                uint32_t a0[2], a1[2], a2[2], a3[2];
#pragma unroll
                for (int i = 0; i < 2; i++)
                    asm volatile(
                        "ldmatrix.sync.aligned.m8n8.x4.shared.b16 "
                        "{%0,%1,%2,%3}, [%4];"
                        : "=r"(a0[i]), "=r"(a1[i]), "=r"(a2[i]), "=r"(a3[i])
                        : "r"(ab[i] + tapd + ks2 * 32));
                const uint2* bk = bp + (size_t)(tap * 2 + ks2) * (NT12 * 32);
#pragma unroll
                for (int j = 0; j < 6; j++) {
                    uint2 bb = __ldg(bk + j * 32);
#pragma unroll
                    for (int i = 0; i < 2; i++)
                        asm volatile(
                            "mma.sync.aligned.m16n8k16.row.col.f32.f16.f16.f32 "
                            "{%0,%1,%2,%3}, {%4,%5,%6,%7}, {%8,%9}, {%0,%1,%2,%3};"
                            : "+f"(acc[i][j][0]), "+f"(acc[i][j][1]),
                              "+f"(acc[i][j][2]), "+f"(acc[i][j][3])
                            : "r"(a0[i]), "r"(a1[i]), "r"(a2[i]), "r"(a3[i]),
                              "r"(bb.x), "r"(bb.y));
                }
            }
        }
    }
    __syncthreads();     /* patch consumed -> Rs may overwrite */

    /* ---- C -> Rs[n][px] (skip n >= 88) ---- */
    {
        const int g8 = lane >> 2;
        const int tg = lane & 3;
#pragma unroll
        for (int i = 0; i < 2; i++) {
            const int px0 = mw * 32 + i * 16 + g8;
#pragma unroll
            for (int j = 0; j < 6; j++) {
                int n = ng * 48 + j * 8 + tg * 2;
                if (ng == 1 && j == 5) continue;   /* n 88..95: pure pad */
                Rs[n * RSTR + px0]           = acc[i][j][0];
                Rs[(n + 1) * RSTR + px0]     = acc[i][j][1];
                Rs[n * RSTR + px0 + 8]       = acc[i][j][2];
                Rs[(n + 1) * RSTR + px0 + 8] = acc[i][j][3];
            }
        }
    }
    __syncthreads();

    /* ---- epilogue: warps 0-5, t = wid/2, 2 px per thread ---- */
    if (wid < 6) {
        const int t = wid >> 1;
        const int nb = t * CHG;
#pragma unroll
        for (int half = 0; half < 2; half++) {
            const int ppx = (wid & 1) * 64 + half * 32 + lane;
#pragma unroll
            for (int j = 0; j < 18; j++) {
                float v = Rs[(nb + j) * RSTR + ppx] + __ldg(b_off + nb + j);
                Rs[(nb + j) * RSTR + ppx] = h2(v);
            }
            float a[9];
            float m = -1e30f;
#pragma unroll
            for (int j = 0; j < 9; j++) {
                a[j] = Rs[(nb + 18 + j) * RSTR + ppx] + __ldg(b_off + nb + 18 + j);
                m = fmaxf(m, a[j]);
            }
            float s = 0.f;
#pragma unroll
            for (int j = 0; j < 9; j++) { a[j] = __expf(a[j] - m); s += a[j]; }
            float inv = 1.f / s;
#pragma unroll
            for (int j = 0; j < 9; j++)
                Rs[(nb + 18 + j) * RSTR + ppx] = h2(a[j] * inv);
        }
    }
    __syncthreads();

    /* ---- stores: f32 to d_out + fp16 staging ---- */
    for (int idx = tid; idx < NOC * 32; idx += 256) {
        int n  = idx >> 5;
        int gq = idx & 31;
        int rr = gq >> 4;
        int c4 = (gq & 15) << 2;
        float4 v = *(float4*)(Rs + n * RSTR + rr * 64 + c4);
        int t = n / CHG;
        int j = n - t * CHG;
        size_t pix = (size_t)(y0 + rr) * W_IMG + x0 + c4;
        __half2 h0 = __floats2half2_rn(v.x, v.y);
        __half2 h1 = __floats2half2_rn(v.z, v.w);
        if (j < 18) {
            size_t o = ((size_t)(b * PT + t) * 18 + j) * HW + pix;
            *(float4*)(out_off + o) = v;
            *(__half2*)(g_offh + o)     = h0;
            *(__half2*)(g_offh + o + 2) = h1;
        } else {
            size_t o = ((size_t)(b * PT + t) * 9 + (j - 18)) * HW + pix;
            *(float4*)(out_aff + o) = v;
            *(__half2*)(g_affh + o)     = h0;
            *(__half2*)(g_affh + o + 2) = h1;
        }
    }
}

/* ---------------- deformable propagation step ---------------- */
__device__ __forceinline__ float samp(const float* __restrict__ fb, int y, int x) {
    if ((unsigned)y < H_IMG && (unsigned)x < W_IMG) return fb[y * W_IMG + x];
    return 0.f;
}

__global__ void __launch_bounds__(256)
prop_kernel(const float* __restrict__ feat_in,
            const float* __restrict__ confid,
            const float* __restrict__ ffix,
            const float* __restrict__ wf,
            const float* __restrict__ bf,
            float* __restrict__ fout,
            float* __restrict__ fout2,
            int t)
{
    int p = blockIdx.x * 256 + threadIdx.x;
    if (p >= NB * HW) return;
    int b   = p / HW;
    int rem = p - b * HW;
    int h   = rem / W_IMG;
    int w   = rem - h * W_IMG;

    const float* fb = feat_in + (size_t)b * HW;
    const __half* ob = g_offh + (size_t)(b * PT + t) * 18 * HW + rem;
    const __half* ab = g_affh + (size_t)(b * PT + t) * 9 * HW + rem;

    float sum = 0.f;
#pragma unroll
    for (int k = 0; k < 9; k++) {
        float dy = __half2float(ob[(size_t)(2 * k) * HW]);
        float dx = __half2float(ob[(size_t)(2 * k + 1) * HW]);
        float a  = __half2float(ab[(size_t)k * HW]);
        float ys = (float)h + (float)(k / 3 - 1) + dy;
        float xs = (float)w + (float)(k % 3 - 1) + dx;
        float y0 = floorf(ys), x0 = floorf(xs);
        float wy = ys - y0,  wx = xs - x0;
        int y0i = (int)y0, x0i = (int)x0;
        float v00 = samp(fb, y0i,     x0i);
        float v01 = samp(fb, y0i,     x0i + 1);
        float v10 = samp(fb, y0i + 1, x0i);
        float v11 = samp(fb, y0i + 1, x0i + 1);
        float v = v00 * (1.f - wy) * (1.f - wx)
                + v01 * (1.f - wy) * wx
                + v10 * wy * (1.f - wx)
                + v11 * wy * wx;
        sum += v * a * wf[k];
    }
    float prop = sum + bf[0];
    float fx   = ffix[p];
    float sg   = (fx > 0.f) ? 1.f : ((fx < 0.f) ? -1.f : 0.f);
    float conf = sg * (1.f / (1.f + __expf(-confid[p])));
    float o    = (1.f - conf) * prop + conf * fx;
    fout[p] = o;
    if (fout2) fout2[p] = o;
}

/* ------------------------- launch ------------------------- */
extern "C" void kernel_launch(void* const* d_in, const int* in_sizes, int n_in,
                              void* d_out, int out_size)
{
    const float* feat_init  = (const float*)d_in[0];
    const float* guidance   = (const float*)d_in[1];
    const float* confidence = (const float*)d_in[2];
    const float* feat_fix   = (const float*)d_in[3];
    const float* w_off      = (const float*)d_in[4];
    const float* b_off      = (const float*)d_in[5];
    const float* w_f        = (const float*)d_in[6];
    const float* b_f        = (const float*)d_in[7];

    float* out = (float*)d_out;
    const size_t NPIX = (size_t)NB * HW;

    float* out_feat = out;
    float* out_list = out + NPIX;
    float* out_off  = out + 4 * NPIX;
    float* out_aff  = out_off + (size_t)NB * PT * 18 * HW;

    cudaFuncSetAttribute(conv_kernel,
                         cudaFuncAttributeMaxDynamicSharedMemorySize, SMEM_TOTAL);

    /* conv stays MY 4th launch (ncu -s5 lands on it, proven R11/R12) */
    reorder_kernel<<<(18 * NT12 * 32 + 255) / 256, 256>>>(w_off);
    dummy_kernel<<<1, 32>>>();
    dummy_kernel<<<1, 32>>>();

    dim3 cg(W_IMG / 64, H_IMG / 2, NB);
    conv_kernel<<<cg, 256, SMEM_TOTAL>>>(guidance, b_off, out_off, out_aff);

    int np = NB * HW;
    int blocks = (np + 255) / 256;
    prop_kernel<<<blocks, 256>>>(feat_init, confidence, feat_fix, w_f, b_f,
                                 out_list, nullptr, 0);
    prop_kernel<<<blocks, 256>>>(out_list, confidence, feat_fix, w_f, b_f,
                                 out_list + NPIX, nullptr, 1);
    prop_kernel<<<blocks, 256>>>(out_list + NPIX, confidence, feat_fix, w_f, b_f,
                                 out_list + 2 * NPIX, out_feat, 2);
}